// round 5
// baseline (speedup 1.0000x reference)
#include <cuda_runtime.h>
#include <cuda_bf16.h>
#include <cstdint>

// Problem constants
#define BB 16
#define KK 256
#define ZZ 128
#define HH 128
#define NROWS (BB * KK)   // 4096

// Scratch (device globals — no allocation allowed)
__device__ __align__(16) float g_m1z[NROWS * ZZ];
__device__ __align__(16) float g_m2z[NROWS * ZZ];
__device__ __align__(16) float g_m  [NROWS * ZZ];

// ---------------------------------------------------------------------------
// K1: m1z = z @ W1^T + b1 ; m2z = z @ W2^T + b2   (rows = 4096, K = 128)
// Block: 32 rows, 256 threads (c = tid&127, ty = tid>>7 splits rows 16/16).
// W chunks staged in shared as [c][kk] with row stride 20 (float4-aligned,
// conflict-free in 8-thread phases). z tile staged whole (broadcast reads).
// ---------------------------------------------------------------------------
__global__ __launch_bounds__(256) void k1_gemm12(
    const float* __restrict__ z,
    const float* __restrict__ W1, const float* __restrict__ b1,
    const float* __restrict__ W2, const float* __restrict__ b2)
{
    __shared__ __align__(16) float zs[32 * 128];     // [r][k]
    __shared__ __align__(16) float wt1[128 * 20];    // [c][kk], chunk of 16 k
    __shared__ __align__(16) float wt2[128 * 20];

    const int tid  = threadIdx.x;
    const int c    = tid & 127;
    const int ty   = tid >> 7;            // 0/1
    const int row0 = blockIdx.x * 32;

    // load z tile (coalesced)
    for (int idx = tid; idx < 32 * 128; idx += 256)
        zs[idx] = z[row0 * 128 + idx];

    float acc1[16], acc2[16];
#pragma unroll
    for (int r = 0; r < 16; r++) { acc1[r] = 0.f; acc2[r] = 0.f; }

    for (int k0 = 0; k0 < 128; k0 += 16) {
        __syncthreads();
        // stage W chunks: 128 c x 16 kk each
        for (int idx = tid; idx < 2048; idx += 256) {
            int cc = idx >> 4, kk = idx & 15;
            wt1[cc * 20 + kk] = W1[cc * 128 + k0 + kk];
            wt2[cc * 20 + kk] = W2[cc * 128 + k0 + kk];
        }
        __syncthreads();

#pragma unroll
        for (int k4 = 0; k4 < 16; k4 += 4) {
            float4 w1 = *(const float4*)&wt1[c * 20 + k4];
            float4 w2 = *(const float4*)&wt2[c * 20 + k4];
#pragma unroll
            for (int r = 0; r < 16; r++) {
                float4 zv = *(const float4*)&zs[(ty * 16 + r) * 128 + k0 + k4];
                acc1[r] += zv.x * w1.x; acc1[r] += zv.y * w1.y;
                acc1[r] += zv.z * w1.z; acc1[r] += zv.w * w1.w;
                acc2[r] += zv.x * w2.x; acc2[r] += zv.y * w2.y;
                acc2[r] += zv.z * w2.z; acc2[r] += zv.w * w2.w;
            }
        }
    }

    const float bb1 = b1[c];
    const float bb2 = b2[c];
#pragma unroll
    for (int r = 0; r < 16; r++) {
        int row = row0 + ty * 16 + r;
        g_m1z[row * 128 + c] = acc1[r] + bb1;
        g_m2z[row * 128 + c] = acc2[r] + bb2;
    }
}

// ---------------------------------------------------------------------------
// K2: g_m[b,i,c] = relu(m1z[b,i,c] + max_{j : P[b,j,i]!=0} m2z[b,j,c])
// Grid (8 i-tiles, 16 batches), 128 threads.
//   c4 = tid&31 handles channels 4*c4..4*c4+3 (float4)
//   sg = tid>>5 handles i = i0 + sg*8 + t,  t in [0,8)
// Neighbor masks built via warp ballot (bit t of smask[j] <-> i0+t).
// Mask bits are warp-uniform -> predicated FMNMX, no divergence.
// ---------------------------------------------------------------------------
__global__ __launch_bounds__(128) void k2_maskmax(const int* __restrict__ P)
{
    __shared__ unsigned smask[256];

    const int tid  = threadIdx.x;
    const int b    = blockIdx.y;
    const int i0   = blockIdx.x * 32;
    const int lane = tid & 31;
    const int wrp  = tid >> 5;

    // build masks: bit t of smask[j] = (P[b, j, i0+t] != 0)
    for (int j = wrp; j < 256; j += 4) {
        int v = P[((b * 256 + j) * 256) + i0 + lane];
        unsigned word = __ballot_sync(0xffffffffu, v != 0);
        if (lane == 0) smask[j] = word;
    }
    __syncthreads();

    const int c4 = tid & 31;
    const int sg = tid >> 5;

    float4 mx[8];
#pragma unroll
    for (int t = 0; t < 8; t++)
        mx[t] = make_float4(-3.0e38f, -3.0e38f, -3.0e38f, -3.0e38f);

    const float4* m2 = (const float4*)g_m2z + (size_t)b * 256 * 32;

#pragma unroll 4
    for (int j = 0; j < 256; j++) {
        float4 v = m2[j * 32 + c4];
        unsigned mw = smask[j] >> (sg * 8);
#pragma unroll
        for (int t = 0; t < 8; t++) {
            if (mw & (1u << t)) {
                mx[t].x = fmaxf(mx[t].x, v.x);
                mx[t].y = fmaxf(mx[t].y, v.y);
                mx[t].z = fmaxf(mx[t].z, v.z);
                mx[t].w = fmaxf(mx[t].w, v.w);
            }
        }
    }

    const float4* m1 = (const float4*)g_m1z + (size_t)b * 256 * 32;
    float4*       gm = (float4*)g_m        + (size_t)b * 256 * 32;
#pragma unroll
    for (int t = 0; t < 8; t++) {
        int i = i0 + sg * 8 + t;
        float4 a = m1[i * 32 + c4];
        float4 o;
        o.x = fmaxf(a.x + mx[t].x, 0.f);
        o.y = fmaxf(a.y + mx[t].y, 0.f);
        o.z = fmaxf(a.z + mx[t].z, 0.f);
        o.w = fmaxf(a.w + mx[t].w, 0.f);
        gm[i * 32 + c4] = o;
    }
}

// ---------------------------------------------------------------------------
// K3: out[row,h] = relu(bu[h] + sum_{f<128} z[row,f]*Wu[h,f]
//                              + sum_{f>=128} m[row,f-128]*Wu[h,f])
// Same structure as K1 with K = 256 (16 chunks of 16).
// ---------------------------------------------------------------------------
__global__ __launch_bounds__(256) void k3_out(
    const float* __restrict__ z,
    const float* __restrict__ Wu, const float* __restrict__ bu,
    float* __restrict__ out)
{
    __shared__ __align__(16) float wt[128 * 20];  // [h][kk], chunk of 16
    __shared__ __align__(16) float xs[32 * 16];   // [r][kk]

    const int tid  = threadIdx.x;
    const int h    = tid & 127;
    const int ty   = tid >> 7;
    const int row0 = blockIdx.x * 32;

    float acc[16];
#pragma unroll
    for (int r = 0; r < 16; r++) acc[r] = 0.f;

    for (int k0 = 0; k0 < 256; k0 += 16) {
        __syncthreads();
        for (int idx = tid; idx < 2048; idx += 256) {
            int hh = idx >> 4, kk = idx & 15;
            wt[hh * 20 + kk] = Wu[hh * 256 + k0 + kk];
        }
        for (int idx = tid; idx < 512; idx += 256) {
            int r = idx >> 4, kk = idx & 15;
            int f = k0 + kk;
            int row = row0 + r;
            xs[r * 16 + kk] = (f < 128) ? z[row * 128 + f]
                                        : g_m[row * 128 + f - 128];
        }
        __syncthreads();

#pragma unroll
        for (int k4 = 0; k4 < 16; k4 += 4) {
            float4 w = *(const float4*)&wt[h * 20 + k4];
#pragma unroll
            for (int r = 0; r < 16; r++) {
                float4 x = *(const float4*)&xs[(ty * 16 + r) * 16 + k4];
                acc[r] += x.x * w.x; acc[r] += x.y * w.y;
                acc[r] += x.z * w.z; acc[r] += x.w * w.w;
            }
        }
    }

    const float bb = bu[h];
#pragma unroll
    for (int r = 0; r < 16; r++) {
        int row = row0 + ty * 16 + r;
        out[row * 128 + h] = fmaxf(acc[r] + bb, 0.f);
    }
}

// ---------------------------------------------------------------------------
// Launch. Inputs (metadata order): z, P, W1, b1, W2, b2, Wu, bu.
// Output: [B, K, H] float32 = 524288 elements.
// ---------------------------------------------------------------------------
extern "C" void kernel_launch(void* const* d_in, const int* in_sizes, int n_in,
                              void* d_out, int out_size)
{
    const float* z  = (const float*)d_in[0];
    const int*   P  = (const int*)  d_in[1];
    const float* W1 = (const float*)d_in[2];
    const float* b1 = (const float*)d_in[3];
    const float* W2 = (const float*)d_in[4];
    const float* b2 = (const float*)d_in[5];
    const float* Wu = (const float*)d_in[6];
    const float* bu = (const float*)d_in[7];
    float* out = (float*)d_out;

    k1_gemm12<<<NROWS / 32, 256>>>(z, W1, b1, W2, b2);

    dim3 g2(KK / 32, BB);   // (8, 16)
    k2_maskmax<<<g2, 128>>>(P);

    k3_out<<<NROWS / 32, 256>>>(z, Wu, bu, out);
}

// round 7
// speedup vs baseline: 1.1860x; 1.1860x over previous
#include <cuda_runtime.h>
#include <cuda_bf16.h>
#include <cstdint>

// Problem constants
#define BB 16
#define KK 256
#define ZZ 128
#define HH 128
#define NROWS (BB * KK)   // 4096

// Scratch (device globals — no allocation allowed)
__device__ __align__(16) float g_m1z[NROWS * ZZ];
__device__ __align__(16) float g_m2z[NROWS * ZZ];
__device__ __align__(16) float g_m  [NROWS * ZZ];

// ---------------------------------------------------------------------------
// K1: m1z = z @ W1^T + b1 ; m2z = z @ W2^T + b2   (rows = 4096, K = 128)
// Block: 16 rows, 256 threads (c = tid&127, ty = tid>>7 -> 8 rows each).
// Grid 256 blocks (>148 SMs), ~28 KB smem, capped regs -> 2-3 blocks/SM.
// ---------------------------------------------------------------------------
__global__ __launch_bounds__(256, 3) void k1_gemm12(
    const float* __restrict__ z,
    const float* __restrict__ W1, const float* __restrict__ b1,
    const float* __restrict__ W2, const float* __restrict__ b2)
{
    __shared__ __align__(16) float zs[16 * 128];     // [r][k]  8 KB
    __shared__ __align__(16) float wt1[128 * 20];    // [c][kk] 10 KB, chunk 16 k
    __shared__ __align__(16) float wt2[128 * 20];

    const int tid  = threadIdx.x;
    const int c    = tid & 127;
    const int ty   = tid >> 7;            // 0/1
    const int row0 = blockIdx.x * 16;

    // load z tile (coalesced)
    for (int idx = tid; idx < 16 * 128; idx += 256)
        zs[idx] = z[row0 * 128 + idx];

    float acc1[8], acc2[8];
#pragma unroll
    for (int r = 0; r < 8; r++) { acc1[r] = 0.f; acc2[r] = 0.f; }

    for (int k0 = 0; k0 < 128; k0 += 16) {
        __syncthreads();
        // stage W chunks: 128 c x 16 kk each
        for (int idx = tid; idx < 2048; idx += 256) {
            int cc = idx >> 4, kk = idx & 15;
            wt1[cc * 20 + kk] = W1[cc * 128 + k0 + kk];
            wt2[cc * 20 + kk] = W2[cc * 128 + k0 + kk];
        }
        __syncthreads();

#pragma unroll
        for (int k4 = 0; k4 < 16; k4 += 4) {
            float4 w1 = *(const float4*)&wt1[c * 20 + k4];
            float4 w2 = *(const float4*)&wt2[c * 20 + k4];
#pragma unroll
            for (int r = 0; r < 8; r++) {
                float4 zv = *(const float4*)&zs[(ty * 8 + r) * 128 + k0 + k4];
                acc1[r] += zv.x * w1.x; acc1[r] += zv.y * w1.y;
                acc1[r] += zv.z * w1.z; acc1[r] += zv.w * w1.w;
                acc2[r] += zv.x * w2.x; acc2[r] += zv.y * w2.y;
                acc2[r] += zv.z * w2.z; acc2[r] += zv.w * w2.w;
            }
        }
    }

    const float bb1 = b1[c];
    const float bb2 = b2[c];
#pragma unroll
    for (int r = 0; r < 8; r++) {
        int row = row0 + ty * 8 + r;
        g_m1z[row * 128 + c] = acc1[r] + bb1;
        g_m2z[row * 128 + c] = acc2[r] + bb2;
    }
}

// ---------------------------------------------------------------------------
// K2: g_m[b,i,c] = relu(m1z[b,i,c] + max_{j : P[b,j,i]!=0} m2z[b,j,c])
// Grid (16 i-tiles of 16, 16 batches) = 256 blocks, 256 threads (8 warps).
//   c4 = tid&31  -> channels 4*c4..4*c4+3 (float4)
//   sg = tid>>5  -> i = i0 + sg*2 + {0,1}
// 16-bit neighbor masks built via one ballot per 2 j-rows.
// ---------------------------------------------------------------------------
__global__ __launch_bounds__(256) void k2_maskmax(const int* __restrict__ P)
{
    __shared__ unsigned smask[256];   // low 16 bits used

    const int tid  = threadIdx.x;
    const int b    = blockIdx.y;
    const int i0   = blockIdx.x * 16;
    const int lane = tid & 31;
    const int wrp  = tid >> 5;        // 0..7

    // build masks: bit t of smask[j] = (P[b, j, i0+t] != 0), t in [0,16)
    // one 32-lane ballot covers two consecutive j rows
    for (int jp = wrp; jp < 128; jp += 8) {
        int j  = 2 * jp + (lane >> 4);
        int io = lane & 15;
        int v  = P[((b * 256 + j) * 256) + i0 + io];
        unsigned word = __ballot_sync(0xffffffffu, v != 0);
        if (lane == 0) {
            smask[2 * jp]     = word & 0xffffu;
            smask[2 * jp + 1] = word >> 16;
        }
    }
    __syncthreads();

    const int c4 = tid & 31;
    const int sg = tid >> 5;

    float4 mx0 = make_float4(-3.0e38f, -3.0e38f, -3.0e38f, -3.0e38f);
    float4 mx1 = mx0;

    const float4* m2 = (const float4*)g_m2z + (size_t)b * 256 * 32;

#pragma unroll 4
    for (int j = 0; j < 256; j++) {
        float4 v = m2[j * 32 + c4];
        unsigned mw = smask[j] >> (sg * 2);
        if (mw & 1u) {
            mx0.x = fmaxf(mx0.x, v.x); mx0.y = fmaxf(mx0.y, v.y);
            mx0.z = fmaxf(mx0.z, v.z); mx0.w = fmaxf(mx0.w, v.w);
        }
        if (mw & 2u) {
            mx1.x = fmaxf(mx1.x, v.x); mx1.y = fmaxf(mx1.y, v.y);
            mx1.z = fmaxf(mx1.z, v.z); mx1.w = fmaxf(mx1.w, v.w);
        }
    }

    const float4* m1 = (const float4*)g_m1z + (size_t)b * 256 * 32;
    float4*       gm = (float4*)g_m        + (size_t)b * 256 * 32;

    {
        int i = i0 + sg * 2;
        float4 a = m1[i * 32 + c4];
        float4 o;
        o.x = fmaxf(a.x + mx0.x, 0.f); o.y = fmaxf(a.y + mx0.y, 0.f);
        o.z = fmaxf(a.z + mx0.z, 0.f); o.w = fmaxf(a.w + mx0.w, 0.f);
        gm[i * 32 + c4] = o;
    }
    {
        int i = i0 + sg * 2 + 1;
        float4 a = m1[i * 32 + c4];
        float4 o;
        o.x = fmaxf(a.x + mx1.x, 0.f); o.y = fmaxf(a.y + mx1.y, 0.f);
        o.z = fmaxf(a.z + mx1.z, 0.f); o.w = fmaxf(a.w + mx1.w, 0.f);
        gm[i * 32 + c4] = o;
    }
}

// ---------------------------------------------------------------------------
// K3: out[row,h] = relu(bu[h] + sum_{f<128} z[row,f]*Wu[h,f]
//                              + sum_{f>=128} m[row,f-128]*Wu[h,f])
// 16 rows/block, grid 256, K = 256 (16 chunks of 16).
// ---------------------------------------------------------------------------
__global__ __launch_bounds__(256, 4) void k3_out(
    const float* __restrict__ z,
    const float* __restrict__ Wu, const float* __restrict__ bu,
    float* __restrict__ out)
{
    __shared__ __align__(16) float wt[128 * 20];  // [h][kk] 10 KB
    __shared__ __align__(16) float xs[16 * 16];   // [r][kk] 1 KB

    const int tid  = threadIdx.x;
    const int h    = tid & 127;
    const int ty   = tid >> 7;
    const int row0 = blockIdx.x * 16;

    float acc[8];
#pragma unroll
    for (int r = 0; r < 8; r++) acc[r] = 0.f;

    for (int k0 = 0; k0 < 256; k0 += 16) {
        __syncthreads();
        for (int idx = tid; idx < 2048; idx += 256) {
            int hh = idx >> 4, kk = idx & 15;
            wt[hh * 20 + kk] = Wu[hh * 256 + k0 + kk];
        }
        if (tid < 256) {
            int r = tid >> 4, kk = tid & 15;
            int f = k0 + kk;
            int row = row0 + r;
            xs[r * 16 + kk] = (f < 128) ? z[row * 128 + f]
                                        : g_m[row * 128 + f - 128];
        }
        __syncthreads();

#pragma unroll
        for (int k4 = 0; k4 < 16; k4 += 4) {
            float4 w = *(const float4*)&wt[h * 20 + k4];
#pragma unroll
            for (int r = 0; r < 8; r++) {
                float4 x = *(const float4*)&xs[(ty * 8 + r) * 16 + k4];
                acc[r] += x.x * w.x; acc[r] += x.y * w.y;
                acc[r] += x.z * w.z; acc[r] += x.w * w.w;
            }
        }
    }

    const float bb = bu[h];
#pragma unroll
    for (int r = 0; r < 8; r++) {
        int row = row0 + ty * 8 + r;
        out[row * 128 + h] = fmaxf(acc[r] + bb, 0.f);
    }
}

// ---------------------------------------------------------------------------
// Launch. Inputs (metadata order): z, P, W1, b1, W2, b2, Wu, bu.
// Output: [B, K, H] float32 = 524288 elements.
// ---------------------------------------------------------------------------
extern "C" void kernel_launch(void* const* d_in, const int* in_sizes, int n_in,
                              void* d_out, int out_size)
{
    const float* z  = (const float*)d_in[0];
    const int*   P  = (const int*)  d_in[1];
    const float* W1 = (const float*)d_in[2];
    const float* b1 = (const float*)d_in[3];
    const float* W2 = (const float*)d_in[4];
    const float* b2 = (const float*)d_in[5];
    const float* Wu = (const float*)d_in[6];
    const float* bu = (const float*)d_in[7];
    float* out = (float*)d_out;

    k1_gemm12<<<NROWS / 16, 256>>>(z, W1, b1, W2, b2);

    dim3 g2(KK / 16, BB);   // (16, 16)
    k2_maskmax<<<g2, 256>>>(P);

    k3_out<<<NROWS / 16, 256>>>(z, Wu, bu, out);
}